// round 1
// baseline (speedup 1.0000x reference)
#include <cuda_runtime.h>
#include <math.h>

// Problem constants
#define Bsz 8
#define Ssz 2048
#define Dsz 1024
#define Hh  8
#define HDi 128
#define Pp  32
#define Msz (Bsz*Ssz)   // 16384

// Scratch (static device arrays — no allocation)
__device__ float g_heads[(size_t)Msz*Dsz];      // 64 MB  (B,S,H*HD) layout
__device__ float g_partial[Bsz*16*Dsz];         // hm partial sums
__device__ float g_hm[Bsz*Dsz];                 // (B, D) head means
__device__ float g_coef[Bsz*Hh*Hh];             // (B, H, H)

// ---------------- SGEMM NT: C[m,n] = sum_k A[m,k]*B[n,k], epilogue variants ----
#define BM 128
#define BN 128
#define BK 16
#define TM 8
#define TN 8

// EPI==1: C = acc * cospi(e0[n])                        (heads projection)
// EPI==2: C = acc + e0[n] + e1[m*N+n]                   (out proj + bias + residual)
template<int EPI>
__global__ void __launch_bounds__(256, 2) gemm_nt(
    const float* __restrict__ A, const float* __restrict__ Bm,
    float* __restrict__ C,
    const float* __restrict__ e0, const float* __restrict__ e1,
    int M, int N, int K)
{
    __shared__ float As[BK][BM];
    __shared__ float Bs[BK][BN];

    const int tid = threadIdx.x;
    const int bm = blockIdx.y * BM;
    const int bn = blockIdx.x * BN;
    const int tx = tid & 15;   // column group (TN*16 = 128)
    const int ty = tid >> 4;   // row group    (TM*16 = 128)

    const int lrow = tid >> 2;        // 0..63
    const int lcol = (tid & 3) * 4;   // 0,4,8,12

    float acc[TM][TN];
    #pragma unroll
    for (int i = 0; i < TM; i++)
        #pragma unroll
        for (int j = 0; j < TN; j++) acc[i][j] = 0.f;

    for (int k0 = 0; k0 < K; k0 += BK) {
        #pragma unroll
        for (int l = 0; l < 2; l++) {
            int r = lrow + l * 64;
            float4 va = *reinterpret_cast<const float4*>(&A[(size_t)(bm + r) * K + k0 + lcol]);
            As[lcol + 0][r] = va.x; As[lcol + 1][r] = va.y;
            As[lcol + 2][r] = va.z; As[lcol + 3][r] = va.w;
            float4 vb = *reinterpret_cast<const float4*>(&Bm[(size_t)(bn + r) * K + k0 + lcol]);
            Bs[lcol + 0][r] = vb.x; Bs[lcol + 1][r] = vb.y;
            Bs[lcol + 2][r] = vb.z; Bs[lcol + 3][r] = vb.w;
        }
        __syncthreads();

        #pragma unroll
        for (int k = 0; k < BK; k++) {
            float a[TM], b[TN];
            float4 a0 = *reinterpret_cast<const float4*>(&As[k][ty * TM]);
            float4 a1 = *reinterpret_cast<const float4*>(&As[k][ty * TM + 4]);
            a[0]=a0.x; a[1]=a0.y; a[2]=a0.z; a[3]=a0.w;
            a[4]=a1.x; a[5]=a1.y; a[6]=a1.z; a[7]=a1.w;
            float4 b0 = *reinterpret_cast<const float4*>(&Bs[k][tx * TN]);
            float4 b1 = *reinterpret_cast<const float4*>(&Bs[k][tx * TN + 4]);
            b[0]=b0.x; b[1]=b0.y; b[2]=b0.z; b[3]=b0.w;
            b[4]=b1.x; b[5]=b1.y; b[6]=b1.z; b[7]=b1.w;
            #pragma unroll
            for (int i = 0; i < TM; i++)
                #pragma unroll
                for (int j = 0; j < TN; j++)
                    acc[i][j] += a[i] * b[j];
        }
        __syncthreads();
    }

    const int n0 = bn + tx * TN;
    if (EPI == 1) {
        float cv[TN];
        #pragma unroll
        for (int j = 0; j < TN; j++) cv[j] = cospif(e0[n0 + j]);
        #pragma unroll
        for (int i = 0; i < TM; i++) {
            int m = bm + ty * TM + i;
            float4 o0, o1;
            o0.x = acc[i][0]*cv[0]; o0.y = acc[i][1]*cv[1];
            o0.z = acc[i][2]*cv[2]; o0.w = acc[i][3]*cv[3];
            o1.x = acc[i][4]*cv[4]; o1.y = acc[i][5]*cv[5];
            o1.z = acc[i][6]*cv[6]; o1.w = acc[i][7]*cv[7];
            *reinterpret_cast<float4*>(&C[(size_t)m * N + n0])     = o0;
            *reinterpret_cast<float4*>(&C[(size_t)m * N + n0 + 4]) = o1;
        }
    } else {
        float bv[TN];
        #pragma unroll
        for (int j = 0; j < TN; j++) bv[j] = e0[n0 + j];
        #pragma unroll
        for (int i = 0; i < TM; i++) {
            int m = bm + ty * TM + i;
            float4 x0 = *reinterpret_cast<const float4*>(&e1[(size_t)m * N + n0]);
            float4 x1 = *reinterpret_cast<const float4*>(&e1[(size_t)m * N + n0 + 4]);
            float4 o0, o1;
            o0.x = acc[i][0] + bv[0] + x0.x; o0.y = acc[i][1] + bv[1] + x0.y;
            o0.z = acc[i][2] + bv[2] + x0.z; o0.w = acc[i][3] + bv[3] + x0.w;
            o1.x = acc[i][4] + bv[4] + x1.x; o1.y = acc[i][5] + bv[5] + x1.y;
            o1.z = acc[i][6] + bv[6] + x1.z; o1.w = acc[i][7] + bv[7] + x1.w;
            *reinterpret_cast<float4*>(&C[(size_t)m * N + n0])     = o0;
            *reinterpret_cast<float4*>(&C[(size_t)m * N + n0 + 4]) = o1;
        }
    }
}

// ---------------- hm = mean over S of heads (two stage) -----------------------
__global__ void hm_stage1() {
    int bi = blockIdx.x;                 // 512 blocks
    int b = bi >> 6, ch = (bi >> 2) & 15, nb = bi & 3;
    int n = nb * 256 + threadIdx.x;
    const float* base = &g_heads[((size_t)(b * Ssz + ch * 128)) * Dsz + n];
    float s = 0.f;
    #pragma unroll 4
    for (int i = 0; i < 128; i++) s += base[(size_t)i * Dsz];
    g_partial[(b * 16 + ch) * Dsz + n] = s;
}

__global__ void hm_stage2() {
    int idx = blockIdx.x * 256 + threadIdx.x;   // 8192 total
    int b = idx >> 10, n = idx & 1023;
    float s = 0.f;
    #pragma unroll
    for (int ch = 0; ch < 16; ch++) s += g_partial[(b * 16 + ch) * Dsz + n];
    g_hm[idx] = s * (1.0f / Ssz);
}

// ---------------- coef (B,H,H) from hm ----------------------------------------
__global__ void coef_kernel(const float* __restrict__ Wp, const float* __restrict__ bp,
                            const float* __restrict__ w1, const float* __restrict__ b1,
                            const float* __restrict__ w2, const float* __restrict__ b2)
{
    __shared__ float hm_s[Dsz];
    __shared__ float pv_s[Hh * Pp];
    __shared__ float inv_s[Hh];
    int b = blockIdx.x;
    int t = threadIdx.x;  // 256
    for (int i = t; i < Dsz; i += 256) hm_s[i] = g_hm[b * Dsz + i];
    __syncthreads();

    {   // pv[h,p] = tanh(hm[h,:] . Wp[h,p,:] + bp[h,p])
        int h = t >> 5, p = t & 31;
        float accv = bp[h * Pp + p];
        const float* w = &Wp[(size_t)(h * Pp + p) * HDi];
        const float* hr = &hm_s[h * HDi];
        #pragma unroll 8
        for (int e = 0; e < HDi; e++) accv += hr[e] * w[e];
        pv_s[t] = tanhf(accv);
    }
    __syncthreads();
    if (t < Hh) {
        float sq = 0.f;
        for (int p = 0; p < Pp; p++) { float v = pv_s[t * Pp + p]; sq += v * v; }
        inv_s[t] = 1.0f / fmaxf(sqrtf(sq), 1e-12f);
    }
    __syncthreads();
    if (t < Hh * Hh) {
        int i = t >> 3, j = t & 7;
        float d = 0.f;
        for (int p = 0; p < Pp; p++) d += pv_s[i * Pp + p] * pv_s[j * Pp + p];
        d *= inv_s[i] * inv_s[j];
        float accv = b2[0];
        #pragma unroll
        for (int k = 0; k < 16; k++) {
            float hx = d * w1[k] + b1[k];
            float g = 0.5f * hx * (1.0f + erff(hx * 0.70710678118654752f));
            accv += g * w2[k];
        }
        // softplus (stable)
        float sp = fmaxf(accv, 0.f) + log1pf(expf(-fabsf(accv)));
        g_coef[b * 64 + t] = (i == j) ? 0.f : 0.1f / (1.0f + sp);
    }
}

// ---------------- in-place cross-head mix: heads <- (I + scale_s*coef) heads ---
__global__ void mix_kernel() {
    __shared__ float cs[64];
    int m0 = blockIdx.x * 2;         // 2 rows per block, same batch (2048 even)
    int b = m0 / Ssz;
    int t = threadIdx.x;
    if (t < 64) cs[t] = g_coef[b * 64 + t];
    __syncthreads();
    int lr = t >> 7, e = t & 127;
    int m = m0 + lr;
    int s = m & (Ssz - 1);
    float scale = (float)(s + 1) * (1.0f / (float)Ssz);
    float* row = &g_heads[(size_t)m * Dsz + e];
    float v[8];
    #pragma unroll
    for (int j = 0; j < 8; j++) v[j] = row[j * HDi];
    #pragma unroll
    for (int i = 0; i < 8; i++) {
        float a = 0.f;
        #pragma unroll
        for (int j = 0; j < 8; j++) a += cs[i * 8 + j] * v[j];
        row[i * HDi] = v[i] + scale * a;
    }
}

// ---------------- in-place LayerNorm over D on d_out ---------------------------
__global__ void ln_kernel(float* __restrict__ y,
                          const float* __restrict__ g, const float* __restrict__ bb)
{
    int m = blockIdx.x;
    int t = threadIdx.x;  // 256
    float4 v = *reinterpret_cast<float4*>(&y[(size_t)m * Dsz + t * 4]);
    float s = v.x + v.y + v.z + v.w;
    float q = v.x * v.x + v.y * v.y + v.z * v.z + v.w * v.w;
    __shared__ float ss[8], qq[8];
    #pragma unroll
    for (int o = 16; o > 0; o >>= 1) {
        s += __shfl_down_sync(0xffffffffu, s, o);
        q += __shfl_down_sync(0xffffffffu, q, o);
    }
    if ((t & 31) == 0) { ss[t >> 5] = s; qq[t >> 5] = q; }
    __syncthreads();
    if (t < 8) {
        s = ss[t]; q = qq[t];
        #pragma unroll
        for (int o = 4; o > 0; o >>= 1) {
            s += __shfl_down_sync(0xffu, s, o);
            q += __shfl_down_sync(0xffu, q, o);
        }
        if (t == 0) { ss[0] = s; qq[0] = q; }
    }
    __syncthreads();
    float mu  = ss[0] * (1.0f / Dsz);
    float var = qq[0] * (1.0f / Dsz) - mu * mu;
    float inv = rsqrtf(var + 1e-5f);
    float4 gg = *reinterpret_cast<const float4*>(&g[t * 4]);
    float4 bv = *reinterpret_cast<const float4*>(&bb[t * 4]);
    v.x = (v.x - mu) * inv * gg.x + bv.x;
    v.y = (v.y - mu) * inv * gg.y + bv.y;
    v.z = (v.z - mu) * inv * gg.z + bv.z;
    v.w = (v.w - mu) * inv * gg.w + bv.w;
    *reinterpret_cast<float4*>(&y[(size_t)m * Dsz + t * 4]) = v;
}

// ---------------- launch -------------------------------------------------------
extern "C" void kernel_launch(void* const* d_in, const int* in_sizes, int n_in,
                              void* d_out, int out_size)
{
    const float* x      = (const float*)d_in[0];
    const float* W_proj = (const float*)d_in[1];
    const float* freqs  = (const float*)d_in[2];
    const float* Wp     = (const float*)d_in[3];
    const float* bp     = (const float*)d_in[4];
    const float* w1     = (const float*)d_in[5];
    const float* b1     = (const float*)d_in[6];
    const float* w2     = (const float*)d_in[7];
    const float* b2     = (const float*)d_in[8];
    const float* Wo     = (const float*)d_in[9];
    const float* bo     = (const float*)d_in[10];
    const float* ln_g   = (const float*)d_in[11];
    const float* ln_b   = (const float*)d_in[12];
    float* out = (float*)d_out;

    float* heads = nullptr;
    cudaGetSymbolAddress((void**)&heads, g_heads);

    dim3 gg(Dsz / BN, Msz / BM);  // (8, 128)

    // heads = (x @ W_projT) * cos(pi*freqs)   [stored as (B,S,H*HD)]
    gemm_nt<1><<<gg, 256>>>(x, W_proj, heads, freqs, nullptr, Msz, Dsz, Dsz);
    // hm = mean_s heads
    hm_stage1<<<512, 256>>>();
    hm_stage2<<<32, 256>>>();
    // coef (B,H,H)
    coef_kernel<<<Bsz, 256>>>(Wp, bp, w1, b1, w2, b2);
    // in-place cross-head mix (includes causal (s+1)/S scale)
    mix_kernel<<<Msz / 2, 256>>>();
    // y = merged @ WoT + bo + x
    gemm_nt<2><<<gg, 256>>>(heads, Wo, out, bo, x, Msz, Dsz, Dsz);
    // LayerNorm in place
    ln_kernel<<<Msz, 256>>>(out, ln_g, ln_b);
}

// round 3
// speedup vs baseline: 3.2825x; 3.2825x over previous
#include <cuda_runtime.h>
#include <math.h>
#include <stdint.h>

// Problem constants
#define Bsz 8
#define Ssz 2048
#define Dsz 1024
#define Hh  8
#define HDi 128
#define Pp  32
#define Msz (Bsz*Ssz)   // 16384

// Scratch (static device arrays — no allocation)
__device__ float g_heads[(size_t)Msz*Dsz];      // 64 MB (B,S,H*HD)
__device__ float g_partial[Bsz*16*Dsz];
__device__ float g_hm[Bsz*Dsz];
__device__ float g_coef[Bsz*Hh*Hh];

// ============ tf32 tensor-core GEMM (mma.sync m16n8k8) ============
// C[m,n] = sum_k A[m,k]*B[n,k]  (NT; B row-major [N][K] == .col K x N)
// EPI==1: C = acc * cospi(e0[n])
// EPI==2: C = acc + e0[n] + e1[m,n]
#define LDA 36   // padded smem stride in floats

__device__ __forceinline__ uint32_t f2tf32(float f) {
    uint32_t u;
    asm("cvt.rna.tf32.f32 %0, %1;" : "=r"(u) : "f"(f));
    return u;
}

template<int EPI>
__global__ void __launch_bounds__(256) gemm_mma(
    const float* __restrict__ A, const float* __restrict__ Bm,
    float* __restrict__ C, const float* __restrict__ e0,
    const float* __restrict__ e1)
{
    __shared__ uint32_t As[128 * LDA];
    __shared__ uint32_t Bs[128 * LDA];
    __shared__ float vec[128];

    const int tid  = threadIdx.x;
    const int lane = tid & 31;
    const int w    = tid >> 5;
    const int g    = lane >> 2;       // 0..7
    const int tg   = lane & 3;        // 0..3
    const int wm   = (w >> 2) * 64;   // 0 / 64
    const int wn   = (w & 3) * 32;    // 0..96
    const int bm   = blockIdx.y * 128;
    const int bn   = blockIdx.x * 128;

    if (tid < 128) {
        float v = e0[bn + tid];
        vec[tid] = (EPI == 1) ? cospif(v) : v;
    }

    const int row_t = tid >> 3;         // 0..31
    const int c4    = (tid & 7) * 4;    // 0,4,...,28
    const float* Ap = A  + (size_t)(bm + row_t) * Dsz + c4;
    const float* Bp = Bm + (size_t)(bn + row_t) * Dsz + c4;

    float acc[4][4][4];
    #pragma unroll
    for (int i = 0; i < 4; i++)
        #pragma unroll
        for (int j = 0; j < 4; j++)
            #pragma unroll
            for (int q = 0; q < 4; q++) acc[i][j][q] = 0.f;

    float4 ra[4], rb[4];
    #pragma unroll
    for (int i = 0; i < 4; i++) {
        ra[i] = *reinterpret_cast<const float4*>(Ap + (size_t)(32 * i) * Dsz);
        rb[i] = *reinterpret_cast<const float4*>(Bp + (size_t)(32 * i) * Dsz);
    }

    for (int kt = 0; kt < 32; kt++) {
        __syncthreads();   // previous compute done before overwrite
        #pragma unroll
        for (int i = 0; i < 4; i++) {
            uint4 ua, ub;
            ua.x = f2tf32(ra[i].x); ua.y = f2tf32(ra[i].y);
            ua.z = f2tf32(ra[i].z); ua.w = f2tf32(ra[i].w);
            ub.x = f2tf32(rb[i].x); ub.y = f2tf32(rb[i].y);
            ub.z = f2tf32(rb[i].z); ub.w = f2tf32(rb[i].w);
            *reinterpret_cast<uint4*>(&As[(row_t + 32 * i) * LDA + c4]) = ua;
            *reinterpret_cast<uint4*>(&Bs[(row_t + 32 * i) * LDA + c4]) = ub;
        }
        __syncthreads();

        if (kt + 1 < 32) {   // prefetch next stage into regs (overlaps compute)
            const int ko = (kt + 1) * 32;
            #pragma unroll
            for (int i = 0; i < 4; i++) {
                ra[i] = *reinterpret_cast<const float4*>(Ap + (size_t)(32 * i) * Dsz + ko);
                rb[i] = *reinterpret_cast<const float4*>(Bp + (size_t)(32 * i) * Dsz + ko);
            }
        }

        #pragma unroll
        for (int kk = 0; kk < 4; kk++) {
            uint32_t a[4][4], b[4][2];
            const int kb = kk * 8;
            #pragma unroll
            for (int mf = 0; mf < 4; mf++) {
                const int r0 = wm + mf * 16 + g;
                a[mf][0] = As[r0 * LDA + kb + tg];
                a[mf][1] = As[(r0 + 8) * LDA + kb + tg];
                a[mf][2] = As[r0 * LDA + kb + tg + 4];
                a[mf][3] = As[(r0 + 8) * LDA + kb + tg + 4];
            }
            #pragma unroll
            for (int nf = 0; nf < 4; nf++) {
                const int n0 = wn + nf * 8 + g;
                b[nf][0] = Bs[n0 * LDA + kb + tg];
                b[nf][1] = Bs[n0 * LDA + kb + tg + 4];
            }
            #pragma unroll
            for (int mf = 0; mf < 4; mf++)
                #pragma unroll
                for (int nf = 0; nf < 4; nf++) {
                    asm volatile(
                        "mma.sync.aligned.m16n8k8.row.col.f32.tf32.tf32.f32 "
                        "{%0,%1,%2,%3}, {%4,%5,%6,%7}, {%8,%9}, {%0,%1,%2,%3};\n"
                        : "+f"(acc[mf][nf][0]), "+f"(acc[mf][nf][1]),
                          "+f"(acc[mf][nf][2]), "+f"(acc[mf][nf][3])
                        : "r"(a[mf][0]), "r"(a[mf][1]), "r"(a[mf][2]), "r"(a[mf][3]),
                          "r"(b[nf][0]), "r"(b[nf][1]));
                }
        }
    }

    // ---- epilogue ----
    #pragma unroll
    for (int mf = 0; mf < 4; mf++) {
        const int r0 = bm + wm + mf * 16 + g;
        #pragma unroll
        for (int nf = 0; nf < 4; nf++) {
            const int cl = wn + nf * 8 + 2 * tg;    // local col (0..127)
            const int cg = bn + cl;                  // global col
            float2 v0, v1;
            if (EPI == 1) {
                float s0 = vec[cl], s1 = vec[cl + 1];
                v0.x = acc[mf][nf][0] * s0; v0.y = acc[mf][nf][1] * s1;
                v1.x = acc[mf][nf][2] * s0; v1.y = acc[mf][nf][3] * s1;
            } else {
                float s0 = vec[cl], s1 = vec[cl + 1];
                float2 x0 = *reinterpret_cast<const float2*>(&e1[(size_t)r0 * Dsz + cg]);
                float2 x1 = *reinterpret_cast<const float2*>(&e1[(size_t)(r0 + 8) * Dsz + cg]);
                v0.x = acc[mf][nf][0] + s0 + x0.x; v0.y = acc[mf][nf][1] + s1 + x0.y;
                v1.x = acc[mf][nf][2] + s0 + x1.x; v1.y = acc[mf][nf][3] + s1 + x1.y;
            }
            *reinterpret_cast<float2*>(&C[(size_t)r0 * Dsz + cg])       = v0;
            *reinterpret_cast<float2*>(&C[(size_t)(r0 + 8) * Dsz + cg]) = v1;
        }
    }
}

// ======================= aux kernels (known-good) =======================
__global__ void hm_stage1() {
    int bi = blockIdx.x;
    int b = bi >> 6, ch = (bi >> 2) & 15, nb = bi & 3;
    int n = nb * 256 + threadIdx.x;
    const float* base = &g_heads[((size_t)(b * Ssz + ch * 128)) * Dsz + n];
    float s = 0.f;
    #pragma unroll 4
    for (int i = 0; i < 128; i++) s += base[(size_t)i * Dsz];
    g_partial[(b * 16 + ch) * Dsz + n] = s;
}

__global__ void hm_stage2() {
    int idx = blockIdx.x * 256 + threadIdx.x;
    int b = idx >> 10, n = idx & 1023;
    float s = 0.f;
    #pragma unroll
    for (int ch = 0; ch < 16; ch++) s += g_partial[(b * 16 + ch) * Dsz + n];
    g_hm[idx] = s * (1.0f / Ssz);
}

__global__ void coef_kernel(const float* __restrict__ Wp, const float* __restrict__ bp,
                            const float* __restrict__ w1, const float* __restrict__ b1,
                            const float* __restrict__ w2, const float* __restrict__ b2)
{
    __shared__ float hm_s[Dsz];
    __shared__ float pv_s[Hh * Pp];
    __shared__ float inv_s[Hh];
    int b = blockIdx.x;
    int t = threadIdx.x;
    for (int i = t; i < Dsz; i += 256) hm_s[i] = g_hm[b * Dsz + i];
    __syncthreads();
    {
        int h = t >> 5, p = t & 31;
        float accv = bp[h * Pp + p];
        const float* w = &Wp[(size_t)(h * Pp + p) * HDi];
        const float* hr = &hm_s[h * HDi];
        #pragma unroll 8
        for (int e = 0; e < HDi; e++) accv += hr[e] * w[e];
        pv_s[t] = tanhf(accv);
    }
    __syncthreads();
    if (t < Hh) {
        float sq = 0.f;
        for (int p = 0; p < Pp; p++) { float v = pv_s[t * Pp + p]; sq += v * v; }
        inv_s[t] = 1.0f / fmaxf(sqrtf(sq), 1e-12f);
    }
    __syncthreads();
    if (t < Hh * Hh) {
        int i = t >> 3, j = t & 7;
        float d = 0.f;
        for (int p = 0; p < Pp; p++) d += pv_s[i * Pp + p] * pv_s[j * Pp + p];
        d *= inv_s[i] * inv_s[j];
        float accv = b2[0];
        #pragma unroll
        for (int k = 0; k < 16; k++) {
            float hx = d * w1[k] + b1[k];
            float gg = 0.5f * hx * (1.0f + erff(hx * 0.70710678118654752f));
            accv += gg * w2[k];
        }
        float sp = fmaxf(accv, 0.f) + log1pf(expf(-fabsf(accv)));
        g_coef[b * 64 + t] = (i == j) ? 0.f : 0.1f / (1.0f + sp);
    }
}

__global__ void mix_kernel() {
    __shared__ float cs[64];
    int m0 = blockIdx.x * 2;
    int b = m0 / Ssz;
    int t = threadIdx.x;
    if (t < 64) cs[t] = g_coef[b * 64 + t];
    __syncthreads();
    int lr = t >> 7, e = t & 127;
    int m = m0 + lr;
    int s = m & (Ssz - 1);
    float scale = (float)(s + 1) * (1.0f / (float)Ssz);
    float* row = &g_heads[(size_t)m * Dsz + e];
    float v[8];
    #pragma unroll
    for (int j = 0; j < 8; j++) v[j] = row[j * HDi];
    #pragma unroll
    for (int i = 0; i < 8; i++) {
        float a = 0.f;
        #pragma unroll
        for (int j = 0; j < 8; j++) a += cs[i * 8 + j] * v[j];
        row[i * HDi] = v[i] + scale * a;
    }
}

__global__ void ln_kernel(float* __restrict__ y,
                          const float* __restrict__ g, const float* __restrict__ bb)
{
    int m = blockIdx.x;
    int t = threadIdx.x;
    float4 v = *reinterpret_cast<float4*>(&y[(size_t)m * Dsz + t * 4]);
    float s = v.x + v.y + v.z + v.w;
    float q = v.x * v.x + v.y * v.y + v.z * v.z + v.w * v.w;
    __shared__ float ss[8], qq[8];
    #pragma unroll
    for (int o = 16; o > 0; o >>= 1) {
        s += __shfl_down_sync(0xffffffffu, s, o);
        q += __shfl_down_sync(0xffffffffu, q, o);
    }
    if ((t & 31) == 0) { ss[t >> 5] = s; qq[t >> 5] = q; }
    __syncthreads();
    if (t < 8) {
        s = ss[t]; q = qq[t];
        #pragma unroll
        for (int o = 4; o > 0; o >>= 1) {
            s += __shfl_down_sync(0xffu, s, o);
            q += __shfl_down_sync(0xffu, q, o);
        }
        if (t == 0) { ss[0] = s; qq[0] = q; }
    }
    __syncthreads();
    float mu  = ss[0] * (1.0f / Dsz);
    float var = qq[0] * (1.0f / Dsz) - mu * mu;
    float inv = rsqrtf(var + 1e-5f);
    float4 gg = *reinterpret_cast<const float4*>(&g[t * 4]);
    float4 bv = *reinterpret_cast<const float4*>(&bb[t * 4]);
    v.x = (v.x - mu) * inv * gg.x + bv.x;
    v.y = (v.y - mu) * inv * gg.y + bv.y;
    v.z = (v.z - mu) * inv * gg.z + bv.z;
    v.w = (v.w - mu) * inv * gg.w + bv.w;
    *reinterpret_cast<float4*>(&y[(size_t)m * Dsz + t * 4]) = v;
}

// ======================= launch =======================
extern "C" void kernel_launch(void* const* d_in, const int* in_sizes, int n_in,
                              void* d_out, int out_size)
{
    const float* x      = (const float*)d_in[0];
    const float* W_proj = (const float*)d_in[1];
    const float* freqs  = (const float*)d_in[2];
    const float* Wp     = (const float*)d_in[3];
    const float* bp     = (const float*)d_in[4];
    const float* w1     = (const float*)d_in[5];
    const float* b1     = (const float*)d_in[6];
    const float* w2     = (const float*)d_in[7];
    const float* b2     = (const float*)d_in[8];
    const float* Wo     = (const float*)d_in[9];
    const float* bo     = (const float*)d_in[10];
    const float* ln_g   = (const float*)d_in[11];
    const float* ln_b   = (const float*)d_in[12];
    float* out = (float*)d_out;

    float* heads = nullptr;
    cudaGetSymbolAddress((void**)&heads, g_heads);

    dim3 gg(Dsz / 128, Msz / 128);  // (8, 128)

    gemm_mma<1><<<gg, 256>>>(x, W_proj, heads, freqs, nullptr);
    hm_stage1<<<512, 256>>>();
    hm_stage2<<<32, 256>>>();
    coef_kernel<<<Bsz, 256>>>(Wp, bp, w1, b1, w2, b2);
    mix_kernel<<<Msz / 2, 256>>>();
    gemm_mma<2><<<gg, 256>>>(heads, Wo, out, bo, x);
    ln_kernel<<<Msz, 256>>>(out, ln_g, ln_b);
}

// round 4
// speedup vs baseline: 4.4032x; 1.3414x over previous
#include <cuda_runtime.h>
#include <cuda_fp16.h>
#include <math.h>
#include <stdint.h>

// Problem constants
#define Bsz 8
#define Ssz 2048
#define Dsz 1024
#define Hh  8
#define HDi 128
#define Pp  32
#define Msz (Bsz*Ssz)   // 16384

// Scratch (static device arrays — no allocation)
__device__ float g_heads[(size_t)Msz*Dsz];      // 64 MB (B,S,H*HD)
__device__ float g_partial[Bsz*16*Dsz];
__device__ float g_hm[Bsz*Dsz];
__device__ float g_coef[Bsz*Hh*Hh];

// ============ fp16 tensor-core GEMM (mma.sync m16n8k16) ============
// C[m,n] = sum_k A[m,k]*B[n,k]  (NT; B row-major [N][K] == .col K x N)
// EPI==1: C = acc * cospi(e0[n])
// EPI==2: C = acc + e0[n] + e1[m,n]
#define LDW 20   // padded smem stride in 32-bit words (= half2 pairs)

__device__ __forceinline__ uint32_t pack_h2(float lo, float hi) {
    uint32_t u;
    asm("cvt.rn.f16x2.f32 %0, %1, %2;" : "=r"(u) : "f"(hi), "f"(lo));
    return u;
}

template<int EPI>
__global__ void __launch_bounds__(256) gemm_mma(
    const float* __restrict__ A, const float* __restrict__ Bm,
    float* __restrict__ C, const float* __restrict__ e0,
    const float* __restrict__ e1)
{
    __shared__ uint32_t As[128 * LDW];
    __shared__ uint32_t Bs[128 * LDW];
    __shared__ float vec[128];

    const int tid  = threadIdx.x;
    const int lane = tid & 31;
    const int w    = tid >> 5;
    const int g    = lane >> 2;       // 0..7
    const int tg   = lane & 3;        // 0..3
    const int wm   = (w >> 2) * 64;   // 0 / 64
    const int wn   = (w & 3) * 32;    // 0..96
    const int bm   = blockIdx.y * 128;
    const int bn   = blockIdx.x * 128;

    if (tid < 128) {
        float v = e0[bn + tid];
        vec[tid] = (EPI == 1) ? cospif(v) : v;
    }

    const int row_t = tid >> 3;         // 0..31
    const int c4    = (tid & 7) * 4;    // float offset 0,4,...,28
    const int cw    = (tid & 7) * 2;    // word offset (half2 pairs)
    const float* Ap = A  + (size_t)(bm + row_t) * Dsz + c4;
    const float* Bp = Bm + (size_t)(bn + row_t) * Dsz + c4;

    float acc[4][4][4];
    #pragma unroll
    for (int i = 0; i < 4; i++)
        #pragma unroll
        for (int j = 0; j < 4; j++)
            #pragma unroll
            for (int q = 0; q < 4; q++) acc[i][j][q] = 0.f;

    float4 ra[4], rb[4];
    #pragma unroll
    for (int i = 0; i < 4; i++) {
        ra[i] = *reinterpret_cast<const float4*>(Ap + (size_t)(32 * i) * Dsz);
        rb[i] = *reinterpret_cast<const float4*>(Bp + (size_t)(32 * i) * Dsz);
    }

    for (int kt = 0; kt < 32; kt++) {
        __syncthreads();   // previous compute done before overwrite
        #pragma unroll
        for (int i = 0; i < 4; i++) {
            uint2 ua, ub;
            ua.x = pack_h2(ra[i].x, ra[i].y);
            ua.y = pack_h2(ra[i].z, ra[i].w);
            ub.x = pack_h2(rb[i].x, rb[i].y);
            ub.y = pack_h2(rb[i].z, rb[i].w);
            *reinterpret_cast<uint2*>(&As[(row_t + 32 * i) * LDW + cw]) = ua;
            *reinterpret_cast<uint2*>(&Bs[(row_t + 32 * i) * LDW + cw]) = ub;
        }
        __syncthreads();

        if (kt + 1 < 32) {   // prefetch next stage into regs (overlaps compute)
            const int ko = (kt + 1) * 32;
            #pragma unroll
            for (int i = 0; i < 4; i++) {
                ra[i] = *reinterpret_cast<const float4*>(Ap + (size_t)(32 * i) * Dsz + ko);
                rb[i] = *reinterpret_cast<const float4*>(Bp + (size_t)(32 * i) * Dsz + ko);
            }
        }

        #pragma unroll
        for (int kk = 0; kk < 2; kk++) {       // two K=16 steps
            const int kb = kk * 8;             // word offset
            uint32_t a[4][4], b[4][2];
            #pragma unroll
            for (int mf = 0; mf < 4; mf++) {
                const int r0 = wm + mf * 16 + g;
                a[mf][0] = As[r0 * LDW + kb + tg];
                a[mf][1] = As[(r0 + 8) * LDW + kb + tg];
                a[mf][2] = As[r0 * LDW + kb + tg + 4];
                a[mf][3] = As[(r0 + 8) * LDW + kb + tg + 4];
            }
            #pragma unroll
            for (int nf = 0; nf < 4; nf++) {
                const int n0 = wn + nf * 8 + g;
                b[nf][0] = Bs[n0 * LDW + kb + tg];
                b[nf][1] = Bs[n0 * LDW + kb + tg + 4];
            }
            #pragma unroll
            for (int mf = 0; mf < 4; mf++)
                #pragma unroll
                for (int nf = 0; nf < 4; nf++) {
                    asm volatile(
                        "mma.sync.aligned.m16n8k16.row.col.f32.f16.f16.f32 "
                        "{%0,%1,%2,%3}, {%4,%5,%6,%7}, {%8,%9}, {%0,%1,%2,%3};\n"
                        : "+f"(acc[mf][nf][0]), "+f"(acc[mf][nf][1]),
                          "+f"(acc[mf][nf][2]), "+f"(acc[mf][nf][3])
                        : "r"(a[mf][0]), "r"(a[mf][1]), "r"(a[mf][2]), "r"(a[mf][3]),
                          "r"(b[nf][0]), "r"(b[nf][1]));
                }
        }
    }

    // ---- epilogue ----
    #pragma unroll
    for (int mf = 0; mf < 4; mf++) {
        const int r0 = bm + wm + mf * 16 + g;
        #pragma unroll
        for (int nf = 0; nf < 4; nf++) {
            const int cl = wn + nf * 8 + 2 * tg;    // local col (0..127)
            const int cg = bn + cl;                  // global col
            float2 v0, v1;
            float s0 = vec[cl], s1 = vec[cl + 1];
            if (EPI == 1) {
                v0.x = acc[mf][nf][0] * s0; v0.y = acc[mf][nf][1] * s1;
                v1.x = acc[mf][nf][2] * s0; v1.y = acc[mf][nf][3] * s1;
            } else {
                float2 x0 = *reinterpret_cast<const float2*>(&e1[(size_t)r0 * Dsz + cg]);
                float2 x1 = *reinterpret_cast<const float2*>(&e1[(size_t)(r0 + 8) * Dsz + cg]);
                v0.x = acc[mf][nf][0] + s0 + x0.x; v0.y = acc[mf][nf][1] + s1 + x0.y;
                v1.x = acc[mf][nf][2] + s0 + x1.x; v1.y = acc[mf][nf][3] + s1 + x1.y;
            }
            *reinterpret_cast<float2*>(&C[(size_t)r0 * Dsz + cg])       = v0;
            *reinterpret_cast<float2*>(&C[(size_t)(r0 + 8) * Dsz + cg]) = v1;
        }
    }
}

// ======================= aux kernels (known-good) =======================
__global__ void hm_stage1() {
    int bi = blockIdx.x;
    int b = bi >> 6, ch = (bi >> 2) & 15, nb = bi & 3;
    int n = nb * 256 + threadIdx.x;
    const float* base = &g_heads[((size_t)(b * Ssz + ch * 128)) * Dsz + n];
    float s = 0.f;
    #pragma unroll 4
    for (int i = 0; i < 128; i++) s += base[(size_t)i * Dsz];
    g_partial[(b * 16 + ch) * Dsz + n] = s;
}

__global__ void hm_stage2() {
    int idx = blockIdx.x * 256 + threadIdx.x;
    int b = idx >> 10, n = idx & 1023;
    float s = 0.f;
    #pragma unroll
    for (int ch = 0; ch < 16; ch++) s += g_partial[(b * 16 + ch) * Dsz + n];
    g_hm[idx] = s * (1.0f / Ssz);
}

__global__ void coef_kernel(const float* __restrict__ Wp, const float* __restrict__ bp,
                            const float* __restrict__ w1, const float* __restrict__ b1,
                            const float* __restrict__ w2, const float* __restrict__ b2)
{
    __shared__ float hm_s[Dsz];
    __shared__ float pv_s[Hh * Pp];
    __shared__ float inv_s[Hh];
    int b = blockIdx.x;
    int t = threadIdx.x;
    for (int i = t; i < Dsz; i += 256) hm_s[i] = g_hm[b * Dsz + i];
    __syncthreads();
    {
        int h = t >> 5, p = t & 31;
        float accv = bp[h * Pp + p];
        const float* w = &Wp[(size_t)(h * Pp + p) * HDi];
        const float* hr = &hm_s[h * HDi];
        #pragma unroll 8
        for (int e = 0; e < HDi; e++) accv += hr[e] * w[e];
        pv_s[t] = tanhf(accv);
    }
    __syncthreads();
    if (t < Hh) {
        float sq = 0.f;
        for (int p = 0; p < Pp; p++) { float v = pv_s[t * Pp + p]; sq += v * v; }
        inv_s[t] = 1.0f / fmaxf(sqrtf(sq), 1e-12f);
    }
    __syncthreads();
    if (t < Hh * Hh) {
        int i = t >> 3, j = t & 7;
        float d = 0.f;
        for (int p = 0; p < Pp; p++) d += pv_s[i * Pp + p] * pv_s[j * Pp + p];
        d *= inv_s[i] * inv_s[j];
        float accv = b2[0];
        #pragma unroll
        for (int k = 0; k < 16; k++) {
            float hx = d * w1[k] + b1[k];
            float gg = 0.5f * hx * (1.0f + erff(hx * 0.70710678118654752f));
            accv += gg * w2[k];
        }
        float sp = fmaxf(accv, 0.f) + log1pf(expf(-fabsf(accv)));
        g_coef[b * 64 + t] = (i == j) ? 0.f : 0.1f / (1.0f + sp);
    }
}

__global__ void mix_kernel() {
    __shared__ float cs[64];
    int m0 = blockIdx.x * 2;
    int b = m0 / Ssz;
    int t = threadIdx.x;
    if (t < 64) cs[t] = g_coef[b * 64 + t];
    __syncthreads();
    int lr = t >> 7, e = t & 127;
    int m = m0 + lr;
    int s = m & (Ssz - 1);
    float scale = (float)(s + 1) * (1.0f / (float)Ssz);
    float* row = &g_heads[(size_t)m * Dsz + e];
    float v[8];
    #pragma unroll
    for (int j = 0; j < 8; j++) v[j] = row[j * HDi];
    #pragma unroll
    for (int i = 0; i < 8; i++) {
        float a = 0.f;
        #pragma unroll
        for (int j = 0; j < 8; j++) a += cs[i * 8 + j] * v[j];
        row[i * HDi] = v[i] + scale * a;
    }
}

__global__ void ln_kernel(float* __restrict__ y,
                          const float* __restrict__ g, const float* __restrict__ bb)
{
    int m = blockIdx.x;
    int t = threadIdx.x;
    float4 v = *reinterpret_cast<float4*>(&y[(size_t)m * Dsz + t * 4]);
    float s = v.x + v.y + v.z + v.w;
    float q = v.x * v.x + v.y * v.y + v.z * v.z + v.w * v.w;
    __shared__ float ss[8], qq[8];
    #pragma unroll
    for (int o = 16; o > 0; o >>= 1) {
        s += __shfl_down_sync(0xffffffffu, s, o);
        q += __shfl_down_sync(0xffffffffu, q, o);
    }
    if ((t & 31) == 0) { ss[t >> 5] = s; qq[t >> 5] = q; }
    __syncthreads();
    if (t < 8) {
        s = ss[t]; q = qq[t];
        #pragma unroll
        for (int o = 4; o > 0; o >>= 1) {
            s += __shfl_down_sync(0xffu, s, o);
            q += __shfl_down_sync(0xffu, q, o);
        }
        if (t == 0) { ss[0] = s; qq[0] = q; }
    }
    __syncthreads();
    float mu  = ss[0] * (1.0f / Dsz);
    float var = qq[0] * (1.0f / Dsz) - mu * mu;
    float inv = rsqrtf(var + 1e-5f);
    float4 gg = *reinterpret_cast<const float4*>(&g[t * 4]);
    float4 bv = *reinterpret_cast<const float4*>(&bb[t * 4]);
    v.x = (v.x - mu) * inv * gg.x + bv.x;
    v.y = (v.y - mu) * inv * gg.y + bv.y;
    v.z = (v.z - mu) * inv * gg.z + bv.z;
    v.w = (v.w - mu) * inv * gg.w + bv.w;
    *reinterpret_cast<float4*>(&y[(size_t)m * Dsz + t * 4]) = v;
}

// ======================= launch =======================
extern "C" void kernel_launch(void* const* d_in, const int* in_sizes, int n_in,
                              void* d_out, int out_size)
{
    const float* x      = (const float*)d_in[0];
    const float* W_proj = (const float*)d_in[1];
    const float* freqs  = (const float*)d_in[2];
    const float* Wp     = (const float*)d_in[3];
    const float* bp     = (const float*)d_in[4];
    const float* w1     = (const float*)d_in[5];
    const float* b1     = (const float*)d_in[6];
    const float* w2     = (const float*)d_in[7];
    const float* b2     = (const float*)d_in[8];
    const float* Wo     = (const float*)d_in[9];
    const float* bo     = (const float*)d_in[10];
    const float* ln_g   = (const float*)d_in[11];
    const float* ln_b   = (const float*)d_in[12];
    float* out = (float*)d_out;

    float* heads = nullptr;
    cudaGetSymbolAddress((void**)&heads, g_heads);

    dim3 gg(Dsz / 128, Msz / 128);  // (8, 128)

    gemm_mma<1><<<gg, 256>>>(x, W_proj, heads, freqs, nullptr);
    hm_stage1<<<512, 256>>>();
    hm_stage2<<<32, 256>>>();
    coef_kernel<<<Bsz, 256>>>(Wp, bp, w1, b1, w2, b2);
    mix_kernel<<<Msz / 2, 256>>>();
    gemm_mma<2><<<gg, 256>>>(heads, Wo, out, bo, x);
    ln_kernel<<<Msz, 256>>>(out, ln_g, ln_b);
}

// round 5
// speedup vs baseline: 5.0307x; 1.1425x over previous
#include <cuda_runtime.h>
#include <cuda_fp16.h>
#include <math.h>
#include <stdint.h>

// Problem constants
#define Bsz 8
#define Ssz 2048
#define Dsz 1024
#define Hh  8
#define HDi 128
#define Pp  32
#define Msz (Bsz*Ssz)   // 16384

// Scratch (static device arrays — no allocation)
__device__ __half g_xh[(size_t)Msz*Dsz];       // 32 MB  x in fp16
__device__ __half g_headsh[(size_t)Msz*Dsz];   // 32 MB  heads fp16 (B,S,H*HD)
__device__ __half g_wph[(size_t)Dsz*Dsz];      // 2 MB   W_proj fp16
__device__ __half g_woh[(size_t)Dsz*Dsz];      // 2 MB   Wo fp16
__device__ float  g_partial[Bsz*16*Dsz];
__device__ float  g_hm[Bsz*Dsz];
__device__ float  g_pm[Bsz*Hh*Pp];
__device__ float  g_coef[Bsz*Hh*Hh];

// ---------------- float -> half convert ----------------
__global__ void f2h_kernel(const float* __restrict__ src, __half* __restrict__ dst) {
    int i = blockIdx.x * 256 + threadIdx.x;     // float4 index
    float4 v = reinterpret_cast<const float4*>(src)[i];
    __half2* d = reinterpret_cast<__half2*>(dst);
    d[2*i]   = __floats2half2_rn(v.x, v.y);
    d[2*i+1] = __floats2half2_rn(v.z, v.w);
}

// ============ fp16 tensor-core GEMM, cp.async 4-ring ============
// C[m,n] = sum_k A[m,k]*B[n,k]  (NT, fp16 operands in gmem)
// EPI==1 (OutT=half):  C = acc * cospi(e0[n])
// EPI==2 (OutT=float): C = acc + e0[n] + e1[m,n]
#define LDW 20                      // padded row stride in 32-bit words
#define STW (128*LDW)               // words per array per stage (2560)
#define GSM ((4*2*STW + 128) * 4)   // 4 stages * (A+B) + vec  = 82432 B

__device__ __forceinline__ void cp16(uint32_t s, const void* g) {
    asm volatile("cp.async.cg.shared.global [%0], [%1], 16;\n" :: "r"(s), "l"(g));
}
__device__ __forceinline__ void cp_commit() {
    asm volatile("cp.async.commit_group;\n" ::: "memory");
}
template<int N>
__device__ __forceinline__ void cp_wait() {
    asm volatile("cp.async.wait_group %0;\n" :: "n"(N) : "memory");
}

template<int EPI, typename OutT>
__global__ void __launch_bounds__(256) gemm_h(
    const __half* __restrict__ A, const __half* __restrict__ Bm,
    OutT* __restrict__ C, const float* __restrict__ e0,
    const float* __restrict__ e1)
{
    extern __shared__ uint32_t sm[];
    float* vec = reinterpret_cast<float*>(sm + 8 * STW);

    const int tid  = threadIdx.x;
    const int lane = tid & 31;
    const int w    = tid >> 5;
    const int g    = lane >> 2;
    const int tg   = lane & 3;
    const int wm   = (w >> 2) * 64;
    const int wn   = (w & 3) * 32;
    const int bm   = blockIdx.y * 128;
    const int bn   = blockIdx.x * 128;

    if (tid < 128) {
        float v = e0[bn + tid];
        vec[tid] = (EPI == 1) ? cospif(v) : v;
    }

    const uint32_t smb = (uint32_t)__cvta_generic_to_shared(sm);
    // loader mapping: 512 16B-chunks per array per stage; 2 per thread
    const int r0l = tid >> 2;          // rows r0l, r0l+64
    const int ccl = tid & 3;           // 16B chunk within row (8 halves)

    auto load_stage = [&](int kt, int s) {
        const uint32_t sA = smb + (uint32_t)(s * 2 * STW) * 4;
        const uint32_t sB = sA + (uint32_t)STW * 4;
        const size_t ko = (size_t)kt * 32 + ccl * 8;
        #pragma unroll
        for (int l = 0; l < 2; l++) {
            const int r = r0l + l * 64;
            const uint32_t so = (uint32_t)(r * LDW + ccl * 4) * 4;
            cp16(sA + so, A  + (size_t)(bm + r) * Dsz + ko);
            cp16(sB + so, Bm + (size_t)(bn + r) * Dsz + ko);
        }
    };

    float acc[4][4][4];
    #pragma unroll
    for (int i = 0; i < 4; i++)
        #pragma unroll
        for (int j = 0; j < 4; j++)
            #pragma unroll
            for (int q = 0; q < 4; q++) acc[i][j][q] = 0.f;

    load_stage(0, 0); cp_commit();
    load_stage(1, 1); cp_commit();

    for (int kt = 0; kt < 32; kt++) {
        if (kt + 2 < 32) { load_stage(kt + 2, (kt + 2) & 3); cp_commit(); cp_wait<2>(); }
        else if (kt + 1 < 32) { cp_wait<1>(); }
        else { cp_wait<0>(); }
        __syncthreads();

        const uint32_t* As = sm + (kt & 3) * 2 * STW;
        const uint32_t* Bs = As + STW;

        #pragma unroll
        for (int kk = 0; kk < 2; kk++) {
            const int kb = kk * 8;
            uint32_t a[4][4], b[4][2];
            #pragma unroll
            for (int mf = 0; mf < 4; mf++) {
                const int r = wm + mf * 16 + g;
                a[mf][0] = As[r * LDW + kb + tg];
                a[mf][1] = As[(r + 8) * LDW + kb + tg];
                a[mf][2] = As[r * LDW + kb + tg + 4];
                a[mf][3] = As[(r + 8) * LDW + kb + tg + 4];
            }
            #pragma unroll
            for (int nf = 0; nf < 4; nf++) {
                const int n0 = wn + nf * 8 + g;
                b[nf][0] = Bs[n0 * LDW + kb + tg];
                b[nf][1] = Bs[n0 * LDW + kb + tg + 4];
            }
            #pragma unroll
            for (int mf = 0; mf < 4; mf++)
                #pragma unroll
                for (int nf = 0; nf < 4; nf++) {
                    asm volatile(
                        "mma.sync.aligned.m16n8k16.row.col.f32.f16.f16.f32 "
                        "{%0,%1,%2,%3}, {%4,%5,%6,%7}, {%8,%9}, {%0,%1,%2,%3};\n"
                        : "+f"(acc[mf][nf][0]), "+f"(acc[mf][nf][1]),
                          "+f"(acc[mf][nf][2]), "+f"(acc[mf][nf][3])
                        : "r"(a[mf][0]), "r"(a[mf][1]), "r"(a[mf][2]), "r"(a[mf][3]),
                          "r"(b[nf][0]), "r"(b[nf][1]));
                }
        }
    }

    // ---- epilogue ----
    #pragma unroll
    for (int mf = 0; mf < 4; mf++) {
        const int r0 = bm + wm + mf * 16 + g;
        #pragma unroll
        for (int nf = 0; nf < 4; nf++) {
            const int cl = wn + nf * 8 + 2 * tg;
            const int cg = bn + cl;
            const float s0 = vec[cl], s1 = vec[cl + 1];
            if (EPI == 1) {
                __half2* Ch = reinterpret_cast<__half2*>(C);
                __half2 h0 = __floats2half2_rn(acc[mf][nf][0] * s0, acc[mf][nf][1] * s1);
                __half2 h1 = __floats2half2_rn(acc[mf][nf][2] * s0, acc[mf][nf][3] * s1);
                Ch[((size_t)r0 * Dsz + cg) >> 1]       = h0;
                Ch[((size_t)(r0 + 8) * Dsz + cg) >> 1] = h1;
            } else {
                float2 x0 = *reinterpret_cast<const float2*>(&e1[(size_t)r0 * Dsz + cg]);
                float2 x1 = *reinterpret_cast<const float2*>(&e1[(size_t)(r0 + 8) * Dsz + cg]);
                float2 v0, v1;
                v0.x = acc[mf][nf][0] + s0 + x0.x; v0.y = acc[mf][nf][1] + s1 + x0.y;
                v1.x = acc[mf][nf][2] + s0 + x1.x; v1.y = acc[mf][nf][3] + s1 + x1.y;
                *reinterpret_cast<float2*>(&((float*)C)[(size_t)r0 * Dsz + cg])       = v0;
                *reinterpret_cast<float2*>(&((float*)C)[(size_t)(r0 + 8) * Dsz + cg]) = v1;
            }
        }
    }
}

// ---------------- hm = mean over S of heads (fp16 src) ----------------
__global__ void hm_stage1() {
    int bi = blockIdx.x;
    int b = bi >> 6, ch = (bi >> 2) & 15, nb = bi & 3;
    int n = nb * 256 + threadIdx.x;
    const __half* base = &g_headsh[((size_t)(b * Ssz + ch * 128)) * Dsz + n];
    float s = 0.f;
    #pragma unroll 4
    for (int i = 0; i < 128; i++) s += __half2float(base[(size_t)i * Dsz]);
    g_partial[(b * 16 + ch) * Dsz + n] = s;
}

__global__ void hm_stage2() {
    int idx = blockIdx.x * 256 + threadIdx.x;
    int b = idx >> 10, n = idx & 1023;
    float s = 0.f;
    #pragma unroll
    for (int ch = 0; ch < 16; ch++) s += g_partial[(b * 16 + ch) * Dsz + n];
    g_hm[idx] = s * (1.0f / Ssz);
}

// ---------------- pv + normalize: grid 64 = (b*8+h), 128 threads --------------
__global__ void pv_kernel(const float* __restrict__ Wp, const float* __restrict__ bp) {
    __shared__ float pvs[Pp];
    const int bh = blockIdx.x;
    const int b = bh >> 3, h = bh & 7;
    const int t = threadIdx.x;
    const int p = t >> 2, q = t & 3;

    const float* hm = &g_hm[b * Dsz + h * HDi];
    const float* wr = &Wp[(size_t)(h * Pp + p) * HDi + q * 32];
    float s = 0.f;
    #pragma unroll 8
    for (int e = 0; e < 32; e++) s += hm[q * 32 + e] * wr[e];
    s += __shfl_xor_sync(0xffffffffu, s, 1);
    s += __shfl_xor_sync(0xffffffffu, s, 2);
    if (q == 0) pvs[p] = tanhf(s + bp[h * Pp + p]);
    __syncthreads();
    if (t < 32) {
        float v = pvs[t];
        float sq = v * v;
        #pragma unroll
        for (int o = 16; o > 0; o >>= 1) sq += __shfl_xor_sync(0xffffffffu, sq, o);
        float inv = 1.0f / fmaxf(sqrtf(sq), 1e-12f);
        g_pm[bh * Pp + t] = v * inv;
    }
}

// ---------------- coef: grid 8, 64 threads ----------------
__global__ void coefb_kernel(const float* __restrict__ w1, const float* __restrict__ b1,
                             const float* __restrict__ w2, const float* __restrict__ b2) {
    const int b = blockIdx.x;
    const int t = threadIdx.x;           // 64
    const int i = t >> 3, j = t & 7;
    const float* pi = &g_pm[(b * Hh + i) * Pp];
    const float* pj = &g_pm[(b * Hh + j) * Pp];
    float d = 0.f;
    #pragma unroll
    for (int p = 0; p < Pp; p++) d += pi[p] * pj[p];
    float accv = b2[0];
    #pragma unroll
    for (int k = 0; k < 16; k++) {
        float hx = d * w1[k] + b1[k];
        float gg = 0.5f * hx * (1.0f + erff(hx * 0.70710678118654752f));
        accv += gg * w2[k];
    }
    float sp = fmaxf(accv, 0.f) + log1pf(expf(-fabsf(accv)));
    g_coef[b * 64 + t] = (i == j) ? 0.f : 0.1f / (1.0f + sp);
}

// ---------------- in-place cross-head mix on fp16 heads ----------------
__global__ void mix_kernel() {
    __shared__ float cs[64];
    int m0 = blockIdx.x * 2;
    int b = m0 / Ssz;
    int t = threadIdx.x;
    if (t < 64) cs[t] = g_coef[b * 64 + t];
    __syncthreads();
    int lr = t >> 7, e = t & 127;
    int m = m0 + lr;
    int s = m & (Ssz - 1);
    float scale = (float)(s + 1) * (1.0f / (float)Ssz);
    __half* row = &g_headsh[(size_t)m * Dsz + e];
    float v[8];
    #pragma unroll
    for (int j = 0; j < 8; j++) v[j] = __half2float(row[j * HDi]);
    #pragma unroll
    for (int i = 0; i < 8; i++) {
        float a = 0.f;
        #pragma unroll
        for (int j = 0; j < 8; j++) a += cs[i * 8 + j] * v[j];
        row[i * HDi] = __float2half(v[i] + scale * a);
    }
}

// ---------------- in-place LayerNorm over D on d_out ----------------
__global__ void ln_kernel(float* __restrict__ y,
                          const float* __restrict__ g, const float* __restrict__ bb)
{
    int m = blockIdx.x;
    int t = threadIdx.x;
    float4 v = *reinterpret_cast<float4*>(&y[(size_t)m * Dsz + t * 4]);
    float s = v.x + v.y + v.z + v.w;
    float q = v.x * v.x + v.y * v.y + v.z * v.z + v.w * v.w;
    __shared__ float ss[8], qq[8];
    #pragma unroll
    for (int o = 16; o > 0; o >>= 1) {
        s += __shfl_down_sync(0xffffffffu, s, o);
        q += __shfl_down_sync(0xffffffffu, q, o);
    }
    if ((t & 31) == 0) { ss[t >> 5] = s; qq[t >> 5] = q; }
    __syncthreads();
    if (t < 8) {
        s = ss[t]; q = qq[t];
        #pragma unroll
        for (int o = 4; o > 0; o >>= 1) {
            s += __shfl_down_sync(0xffu, s, o);
            q += __shfl_down_sync(0xffu, q, o);
        }
        if (t == 0) { ss[0] = s; qq[0] = q; }
    }
    __syncthreads();
    float mu  = ss[0] * (1.0f / Dsz);
    float var = qq[0] * (1.0f / Dsz) - mu * mu;
    float inv = rsqrtf(var + 1e-5f);
    float4 gg = *reinterpret_cast<const float4*>(&g[t * 4]);
    float4 bv = *reinterpret_cast<const float4*>(&bb[t * 4]);
    v.x = (v.x - mu) * inv * gg.x + bv.x;
    v.y = (v.y - mu) * inv * gg.y + bv.y;
    v.z = (v.z - mu) * inv * gg.z + bv.z;
    v.w = (v.w - mu) * inv * gg.w + bv.w;
    *reinterpret_cast<float4*>(&y[(size_t)m * Dsz + t * 4]) = v;
}

// ======================= launch =======================
extern "C" void kernel_launch(void* const* d_in, const int* in_sizes, int n_in,
                              void* d_out, int out_size)
{
    const float* x      = (const float*)d_in[0];
    const float* W_proj = (const float*)d_in[1];
    const float* freqs  = (const float*)d_in[2];
    const float* Wp     = (const float*)d_in[3];
    const float* bp     = (const float*)d_in[4];
    const float* w1     = (const float*)d_in[5];
    const float* b1     = (const float*)d_in[6];
    const float* w2     = (const float*)d_in[7];
    const float* b2     = (const float*)d_in[8];
    const float* Wo     = (const float*)d_in[9];
    const float* bo     = (const float*)d_in[10];
    const float* ln_g   = (const float*)d_in[11];
    const float* ln_b   = (const float*)d_in[12];
    float* out = (float*)d_out;

    __half *xh = nullptr, *headsh = nullptr, *wph = nullptr, *woh = nullptr;
    cudaGetSymbolAddress((void**)&xh, g_xh);
    cudaGetSymbolAddress((void**)&headsh, g_headsh);
    cudaGetSymbolAddress((void**)&wph, g_wph);
    cudaGetSymbolAddress((void**)&woh, g_woh);

    cudaFuncSetAttribute(gemm_h<1, __half>, cudaFuncAttributeMaxDynamicSharedMemorySize, GSM);
    cudaFuncSetAttribute(gemm_h<2, float>,  cudaFuncAttributeMaxDynamicSharedMemorySize, GSM);

    // converts
    f2h_kernel<<<(Msz * Dsz) / 4 / 256, 256>>>(x, xh);
    f2h_kernel<<<(Dsz * Dsz) / 4 / 256, 256>>>(W_proj, wph);
    f2h_kernel<<<(Dsz * Dsz) / 4 / 256, 256>>>(Wo, woh);

    dim3 gg(Dsz / 128, Msz / 128);  // (8, 128)

    gemm_h<1, __half><<<gg, 256, GSM>>>(xh, wph, headsh, freqs, nullptr);
    hm_stage1<<<512, 256>>>();
    hm_stage2<<<32, 256>>>();
    pv_kernel<<<Bsz * Hh, 128>>>(Wp, bp);
    coefb_kernel<<<Bsz, 64>>>(w1, b1, w2, b2);
    mix_kernel<<<Msz / 2, 256>>>();
    gemm_h<2, float><<<gg, 256, GSM>>>(headsh, woh, out, bo, x);
    ln_kernel<<<Msz, 256>>>(out, ln_g, ln_b);
}

// round 6
// speedup vs baseline: 5.4848x; 1.0903x over previous
#include <cuda_runtime.h>
#include <cuda_fp16.h>
#include <math.h>
#include <stdint.h>

// Problem constants
#define Bsz 8
#define Ssz 2048
#define Dsz 1024
#define Hh  8
#define HDi 128
#define Pp  32
#define Msz (Bsz*Ssz)   // 16384

// Scratch (static device arrays — no allocation)
__device__ __half g_xh[(size_t)Msz*Dsz];       // 32 MB  x in fp16
__device__ __half g_headsh[(size_t)Msz*Dsz];   // 32 MB  heads fp16 (B,S,H*HD)
__device__ __half g_wph[(size_t)Dsz*Dsz];      // 2 MB   W_proj fp16
__device__ __half g_woh[(size_t)Dsz*Dsz];      // 2 MB   Wo fp16
__device__ float  g_partial[Bsz*16*Dsz];
__device__ float  g_hm[Bsz*Dsz];
__device__ float  g_pm[Bsz*Hh*Pp];
__device__ float  g_coef[Bsz*Hh*Hh];

// ---------------- float -> half convert ----------------
__global__ void f2h_kernel(const float* __restrict__ src, __half* __restrict__ dst) {
    int i = blockIdx.x * 256 + threadIdx.x;     // float4 index
    float4 v = reinterpret_cast<const float4*>(src)[i];
    __half2* d = reinterpret_cast<__half2*>(dst);
    d[2*i]   = __floats2half2_rn(v.x, v.y);
    d[2*i+1] = __floats2half2_rn(v.z, v.w);
}

// ============ fp16 tensor-core GEMM, cp.async 4-ring + ldmatrix ============
// C[m,n] = sum_k A[m,k]*B[n,k]  (NT, fp16 operands in gmem)
// EPI==1 (OutT=half):  C = acc * cospi(e0[n])
// EPI==2 (OutT=float): C = acc + e0[n] + e1[m,n]
#define LDW 20                      // padded row stride in 32-bit words
#define STW (128*LDW)               // words per array per stage (2560)
#define GSM ((4*2*STW + 128) * 4)   // 4 stages * (A+B) + vec  = 82432 B

__device__ __forceinline__ void cp16(uint32_t s, const void* g) {
    asm volatile("cp.async.cg.shared.global [%0], [%1], 16;\n" :: "r"(s), "l"(g));
}
__device__ __forceinline__ void cp_commit() {
    asm volatile("cp.async.commit_group;\n" ::: "memory");
}
template<int N>
__device__ __forceinline__ void cp_wait() {
    asm volatile("cp.async.wait_group %0;\n" :: "n"(N) : "memory");
}
__device__ __forceinline__ void ldsm4(uint32_t& r0, uint32_t& r1, uint32_t& r2, uint32_t& r3,
                                      uint32_t addr) {
    asm volatile("ldmatrix.sync.aligned.m8n8.x4.shared.b16 {%0,%1,%2,%3}, [%4];"
                 : "=r"(r0), "=r"(r1), "=r"(r2), "=r"(r3) : "r"(addr));
}

template<int EPI, typename OutT>
__global__ void __launch_bounds__(256) gemm_h(
    const __half* __restrict__ A, const __half* __restrict__ Bm,
    OutT* __restrict__ C, const float* __restrict__ e0,
    const float* __restrict__ e1)
{
    extern __shared__ uint32_t sm[];
    float* vec = reinterpret_cast<float*>(sm + 8 * STW);

    const int tid  = threadIdx.x;
    const int lane = tid & 31;
    const int w    = tid >> 5;
    const int g    = lane >> 2;
    const int tg   = lane & 3;
    const int wm   = (w >> 2) * 64;
    const int wn   = (w & 3) * 32;
    const int bm   = blockIdx.y * 128;
    const int bn   = blockIdx.x * 128;

    if (tid < 128) {
        float v = e0[bn + tid];
        vec[tid] = (EPI == 1) ? cospif(v) : v;
    }

    const uint32_t smb = (uint32_t)__cvta_generic_to_shared(sm);
    // loader mapping: 512 16B-chunks per array per stage; 2 per thread
    const int r0l = tid >> 2;          // rows r0l, r0l+64
    const int ccl = tid & 3;           // 16B chunk within row (8 halves)

    auto load_stage = [&](int kt, int s) {
        const uint32_t sA = smb + (uint32_t)(s * 2 * STW) * 4;
        const uint32_t sB = sA + (uint32_t)STW * 4;
        const size_t ko = (size_t)kt * 32 + ccl * 8;
        #pragma unroll
        for (int l = 0; l < 2; l++) {
            const int r = r0l + l * 64;
            const uint32_t so = (uint32_t)(r * LDW + ccl * 4) * 4;
            cp16(sA + so, A  + (size_t)(bm + r) * Dsz + ko);
            cp16(sB + so, Bm + (size_t)(bn + r) * Dsz + ko);
        }
    };

    // ldmatrix per-lane word offsets (within an A/B stage array)
    const int l8  = lane & 7;
    const int grp = lane >> 3;   // 0..3
    uint32_t aoff[4], boff[2];
    #pragma unroll
    for (int mf = 0; mf < 4; mf++) {
        const int row = wm + mf * 16 + l8 + (grp & 1) * 8;
        aoff[mf] = (uint32_t)(row * LDW + (grp >> 1) * 4) * 4;
    }
    #pragma unroll
    for (int p = 0; p < 2; p++) {
        const int row = wn + p * 16 + l8 + (grp >> 1) * 8;
        boff[p] = (uint32_t)(row * LDW + (grp & 1) * 4) * 4;
    }

    float acc[4][4][4];
    #pragma unroll
    for (int i = 0; i < 4; i++)
        #pragma unroll
        for (int j = 0; j < 4; j++)
            #pragma unroll
            for (int q = 0; q < 4; q++) acc[i][j][q] = 0.f;

    load_stage(0, 0); cp_commit();
    load_stage(1, 1); cp_commit();

    for (int kt = 0; kt < 32; kt++) {
        if (kt + 2 < 32) { load_stage(kt + 2, (kt + 2) & 3); cp_commit(); cp_wait<2>(); }
        else if (kt + 1 < 32) { cp_wait<1>(); }
        else { cp_wait<0>(); }
        __syncthreads();

        const uint32_t stA = smb + (uint32_t)((kt & 3) * 2 * STW) * 4;
        const uint32_t stB = stA + (uint32_t)STW * 4;

        #pragma unroll
        for (int kk = 0; kk < 2; kk++) {
            const uint32_t kbb = kk * 32;   // 8 words
            uint32_t a[4][4], b[4][2];
            #pragma unroll
            for (int mf = 0; mf < 4; mf++)
                ldsm4(a[mf][0], a[mf][1], a[mf][2], a[mf][3], stA + aoff[mf] + kbb);
            #pragma unroll
            for (int p = 0; p < 2; p++)
                ldsm4(b[2*p][0], b[2*p][1], b[2*p+1][0], b[2*p+1][1], stB + boff[p] + kbb);
            #pragma unroll
            for (int mf = 0; mf < 4; mf++)
                #pragma unroll
                for (int nf = 0; nf < 4; nf++) {
                    asm volatile(
                        "mma.sync.aligned.m16n8k16.row.col.f32.f16.f16.f32 "
                        "{%0,%1,%2,%3}, {%4,%5,%6,%7}, {%8,%9}, {%0,%1,%2,%3};\n"
                        : "+f"(acc[mf][nf][0]), "+f"(acc[mf][nf][1]),
                          "+f"(acc[mf][nf][2]), "+f"(acc[mf][nf][3])
                        : "r"(a[mf][0]), "r"(a[mf][1]), "r"(a[mf][2]), "r"(a[mf][3]),
                          "r"(b[nf][0]), "r"(b[nf][1]));
                }
        }
    }

    // ---- epilogue ----
    #pragma unroll
    for (int mf = 0; mf < 4; mf++) {
        const int r0 = bm + wm + mf * 16 + g;
        #pragma unroll
        for (int nf = 0; nf < 4; nf++) {
            const int cl = wn + nf * 8 + 2 * tg;
            const int cg = bn + cl;
            const float s0 = vec[cl], s1 = vec[cl + 1];
            if (EPI == 1) {
                __half2* Ch = reinterpret_cast<__half2*>(C);
                __half2 h0 = __floats2half2_rn(acc[mf][nf][0] * s0, acc[mf][nf][1] * s1);
                __half2 h1 = __floats2half2_rn(acc[mf][nf][2] * s0, acc[mf][nf][3] * s1);
                Ch[((size_t)r0 * Dsz + cg) >> 1]       = h0;
                Ch[((size_t)(r0 + 8) * Dsz + cg) >> 1] = h1;
            } else {
                float2 x0 = *reinterpret_cast<const float2*>(&e1[(size_t)r0 * Dsz + cg]);
                float2 x1 = *reinterpret_cast<const float2*>(&e1[(size_t)(r0 + 8) * Dsz + cg]);
                float2 v0, v1;
                v0.x = acc[mf][nf][0] + s0 + x0.x; v0.y = acc[mf][nf][1] + s1 + x0.y;
                v1.x = acc[mf][nf][2] + s0 + x1.x; v1.y = acc[mf][nf][3] + s1 + x1.y;
                *reinterpret_cast<float2*>(&((float*)C)[(size_t)r0 * Dsz + cg])       = v0;
                *reinterpret_cast<float2*>(&((float*)C)[(size_t)(r0 + 8) * Dsz + cg]) = v1;
            }
        }
    }
}

// ---------------- hm = mean over S of heads (fp16 src) ----------------
__global__ void hm_stage1() {
    int bi = blockIdx.x;
    int b = bi >> 6, ch = (bi >> 2) & 15, nb = bi & 3;
    int n = nb * 256 + threadIdx.x;
    const __half* base = &g_headsh[((size_t)(b * Ssz + ch * 128)) * Dsz + n];
    float s = 0.f;
    #pragma unroll 4
    for (int i = 0; i < 128; i++) s += __half2float(base[(size_t)i * Dsz]);
    g_partial[(b * 16 + ch) * Dsz + n] = s;
}

__global__ void hm_stage2() {
    int idx = blockIdx.x * 256 + threadIdx.x;
    int b = idx >> 10, n = idx & 1023;
    float s = 0.f;
    #pragma unroll
    for (int ch = 0; ch < 16; ch++) s += g_partial[(b * 16 + ch) * Dsz + n];
    g_hm[idx] = s * (1.0f / Ssz);
}

// ---------------- pv + normalize: grid 64 = (b*8+h), 128 threads --------------
__global__ void pv_kernel(const float* __restrict__ Wp, const float* __restrict__ bp) {
    __shared__ float pvs[Pp];
    const int bh = blockIdx.x;
    const int b = bh >> 3, h = bh & 7;
    const int t = threadIdx.x;
    const int p = t >> 2, q = t & 3;

    const float* hm = &g_hm[b * Dsz + h * HDi];
    const float* wr = &Wp[(size_t)(h * Pp + p) * HDi + q * 32];
    float s = 0.f;
    #pragma unroll 8
    for (int e = 0; e < 32; e++) s += hm[q * 32 + e] * wr[e];
    s += __shfl_xor_sync(0xffffffffu, s, 1);
    s += __shfl_xor_sync(0xffffffffu, s, 2);
    if (q == 0) pvs[p] = tanhf(s + bp[h * Pp + p]);
    __syncthreads();
    if (t < 32) {
        float v = pvs[t];
        float sq = v * v;
        #pragma unroll
        for (int o = 16; o > 0; o >>= 1) sq += __shfl_xor_sync(0xffffffffu, sq, o);
        float inv = 1.0f / fmaxf(sqrtf(sq), 1e-12f);
        g_pm[bh * Pp + t] = v * inv;
    }
}

// ---------------- coef: grid 8, 64 threads ----------------
__global__ void coefb_kernel(const float* __restrict__ w1, const float* __restrict__ b1,
                             const float* __restrict__ w2, const float* __restrict__ b2) {
    const int b = blockIdx.x;
    const int t = threadIdx.x;           // 64
    const int i = t >> 3, j = t & 7;
    const float* pi = &g_pm[(b * Hh + i) * Pp];
    const float* pj = &g_pm[(b * Hh + j) * Pp];
    float d = 0.f;
    #pragma unroll
    for (int p = 0; p < Pp; p++) d += pi[p] * pj[p];
    float accv = b2[0];
    #pragma unroll
    for (int k = 0; k < 16; k++) {
        float hx = d * w1[k] + b1[k];
        float gg = 0.5f * hx * (1.0f + erff(hx * 0.70710678118654752f));
        accv += gg * w2[k];
    }
    float sp = fmaxf(accv, 0.f) + log1pf(expf(-fabsf(accv)));
    g_coef[b * 64 + t] = (i == j) ? 0.f : 0.1f / (1.0f + sp);
}

// ---------------- in-place cross-head mix on fp16 heads ----------------
__global__ void mix_kernel() {
    __shared__ float cs[64];
    int m0 = blockIdx.x * 2;
    int b = m0 / Ssz;
    int t = threadIdx.x;
    if (t < 64) cs[t] = g_coef[b * 64 + t];
    __syncthreads();
    int lr = t >> 7, e = t & 127;
    int m = m0 + lr;
    int s = m & (Ssz - 1);
    float scale = (float)(s + 1) * (1.0f / (float)Ssz);
    __half* row = &g_headsh[(size_t)m * Dsz + e];
    float v[8];
    #pragma unroll
    for (int j = 0; j < 8; j++) v[j] = __half2float(row[j * HDi]);
    #pragma unroll
    for (int i = 0; i < 8; i++) {
        float a = 0.f;
        #pragma unroll
        for (int j = 0; j < 8; j++) a += cs[i * 8 + j] * v[j];
        row[i * HDi] = __float2half(v[i] + scale * a);
    }
}

// ---------------- in-place LayerNorm over D on d_out ----------------
__global__ void ln_kernel(float* __restrict__ y,
                          const float* __restrict__ g, const float* __restrict__ bb)
{
    int m = blockIdx.x;
    int t = threadIdx.x;
    float4 v = *reinterpret_cast<float4*>(&y[(size_t)m * Dsz + t * 4]);
    float s = v.x + v.y + v.z + v.w;
    float q = v.x * v.x + v.y * v.y + v.z * v.z + v.w * v.w;
    __shared__ float ss[8], qq[8];
    #pragma unroll
    for (int o = 16; o > 0; o >>= 1) {
        s += __shfl_down_sync(0xffffffffu, s, o);
        q += __shfl_down_sync(0xffffffffu, q, o);
    }
    if ((t & 31) == 0) { ss[t >> 5] = s; qq[t >> 5] = q; }
    __syncthreads();
    if (t < 8) {
        s = ss[t]; q = qq[t];
        #pragma unroll
        for (int o = 4; o > 0; o >>= 1) {
            s += __shfl_down_sync(0xffu, s, o);
            q += __shfl_down_sync(0xffu, q, o);
        }
        if (t == 0) { ss[0] = s; qq[0] = q; }
    }
    __syncthreads();
    float mu  = ss[0] * (1.0f / Dsz);
    float var = qq[0] * (1.0f / Dsz) - mu * mu;
    float inv = rsqrtf(var + 1e-5f);
    float4 gg = *reinterpret_cast<const float4*>(&g[t * 4]);
    float4 bv = *reinterpret_cast<const float4*>(&bb[t * 4]);
    v.x = (v.x - mu) * inv * gg.x + bv.x;
    v.y = (v.y - mu) * inv * gg.y + bv.y;
    v.z = (v.z - mu) * inv * gg.z + bv.z;
    v.w = (v.w - mu) * inv * gg.w + bv.w;
    *reinterpret_cast<float4*>(&y[(size_t)m * Dsz + t * 4]) = v;
}

// ======================= launch =======================
extern "C" void kernel_launch(void* const* d_in, const int* in_sizes, int n_in,
                              void* d_out, int out_size)
{
    const float* x      = (const float*)d_in[0];
    const float* W_proj = (const float*)d_in[1];
    const float* freqs  = (const float*)d_in[2];
    const float* Wp     = (const float*)d_in[3];
    const float* bp     = (const float*)d_in[4];
    const float* w1     = (const float*)d_in[5];
    const float* b1     = (const float*)d_in[6];
    const float* w2     = (const float*)d_in[7];
    const float* b2     = (const float*)d_in[8];
    const float* Wo     = (const float*)d_in[9];
    const float* bo     = (const float*)d_in[10];
    const float* ln_g   = (const float*)d_in[11];
    const float* ln_b   = (const float*)d_in[12];
    float* out = (float*)d_out;

    __half *xh = nullptr, *headsh = nullptr, *wph = nullptr, *woh = nullptr;
    cudaGetSymbolAddress((void**)&xh, g_xh);
    cudaGetSymbolAddress((void**)&headsh, g_headsh);
    cudaGetSymbolAddress((void**)&wph, g_wph);
    cudaGetSymbolAddress((void**)&woh, g_woh);

    cudaFuncSetAttribute(gemm_h<1, __half>, cudaFuncAttributeMaxDynamicSharedMemorySize, GSM);
    cudaFuncSetAttribute(gemm_h<2, float>,  cudaFuncAttributeMaxDynamicSharedMemorySize, GSM);

    // converts
    f2h_kernel<<<(Msz * Dsz) / 4 / 256, 256>>>(x, xh);
    f2h_kernel<<<(Dsz * Dsz) / 4 / 256, 256>>>(W_proj, wph);
    f2h_kernel<<<(Dsz * Dsz) / 4 / 256, 256>>>(Wo, woh);

    dim3 gg(Dsz / 128, Msz / 128);  // (8, 128)

    gemm_h<1, __half><<<gg, 256, GSM>>>(xh, wph, headsh, freqs, nullptr);
    hm_stage1<<<512, 256>>>();
    hm_stage2<<<32, 256>>>();
    pv_kernel<<<Bsz * Hh, 128>>>(Wp, bp);
    coefb_kernel<<<Bsz, 64>>>(w1, b1, w2, b2);
    mix_kernel<<<Msz / 2, 256>>>();
    gemm_h<2, float><<<gg, 256, GSM>>>(headsh, woh, out, bo, x);
    ln_kernel<<<Msz, 256>>>(out, ln_g, ln_b);
}